// round 5
// baseline (speedup 1.0000x reference)
#include <cuda_runtime.h>
#include <cuda_fp16.h>
#include <cstdint>

#define N_NODES   20000
#define M_PAD     20096      // 157 * 128
#define IN_DIM    256
#define OUT_DIM   256
#define FOLD_DIM  128        // 32 q-groups * 4 bases
#define K_DIM     1024       // 8 relations * 128

// Scratch (static device globals — no allocation allowed)
__device__ float  g_hf[N_NODES * FOLD_DIM];        // folded h  [N, 128]
__device__ float  g_U [(size_t)M_PAD * K_DIM];     // aggregated [M_PAD, 1024]
__device__ __half g_Bt[(size_t)OUT_DIM * K_DIM];   // basis^T, K-major, fp16

// ---------------------------------------------------------------------------
// Kernel 1: fold h with w_comp.  hf[n, q*4+b] = sum_p h[n, q*8+p] * w_comp[p,b]
// ---------------------------------------------------------------------------
__global__ void fold_kernel(const float* __restrict__ h,
                            const float* __restrict__ w_comp, int N) {
    __shared__ float wc[32];
    if (threadIdx.x < 32) wc[threadIdx.x] = w_comp[threadIdx.x];
    __syncthreads();

    int idx = blockIdx.x * blockDim.x + threadIdx.x;
    if (idx >= N * 32) return;
    int n = idx >> 5;
    int q = idx & 31;

    const float4* hp = reinterpret_cast<const float4*>(h + (size_t)n * IN_DIM + q * 8);
    float4 h0 = hp[0];
    float4 h1 = hp[1];
    float hv[8] = {h0.x, h0.y, h0.z, h0.w, h1.x, h1.y, h1.z, h1.w};

    float4 o;
    float* op = &o.x;
    #pragma unroll
    for (int b = 0; b < 4; b++) {
        float s = 0.f;
        #pragma unroll
        for (int p = 0; p < 8; p++) s += hv[p] * wc[p * 4 + b];
        op[b] = s;
    }
    *reinterpret_cast<float4*>(g_hf + (size_t)n * FOLD_DIM + q * 4) = o;
}

// ---------------------------------------------------------------------------
// Kernel 2: transpose basis [1024,256] -> g_Bt [256,1024] (K-major) as fp16.
// ---------------------------------------------------------------------------
__global__ void transpose_kernel(const float* __restrict__ basis) {
    __shared__ float t[32][33];
    int bx = blockIdx.x;   // k tile (32)
    int by = blockIdx.y;   // n tile (8)
    int x = threadIdx.x;   // 0..31
    int y = threadIdx.y;   // 0..7
    #pragma unroll
    for (int i = 0; i < 4; i++)
        t[y + i * 8][x] = basis[(size_t)(bx * 32 + y + i * 8) * OUT_DIM + by * 32 + x];
    __syncthreads();
    #pragma unroll
    for (int i = 0; i < 4; i++)
        g_Bt[(size_t)(by * 32 + y + i * 8) * K_DIM + bx * 32 + x] =
            __float2half_rn(t[x][y + i * 8]);
}

// ---------------------------------------------------------------------------
// Kernel 3: edge scatter. One warp per edge. red.global.add.v4.f32
// ---------------------------------------------------------------------------
__global__ void scatter_kernel(const int* __restrict__ src,
                               const int* __restrict__ dst,
                               const int* __restrict__ etype, int E) {
    int warp = (blockIdx.x * blockDim.x + threadIdx.x) >> 5;
    int lane = threadIdx.x & 31;
    if (warp >= E) return;

    int s = __ldg(src + warp);
    int d = __ldg(dst + warp);
    int r = __ldg(etype + warp);

    float4 v = reinterpret_cast<const float4*>(g_hf + (size_t)s * FOLD_DIM)[lane];
    float* up = g_U + (size_t)d * K_DIM + r * FOLD_DIM + lane * 4;
    asm volatile("red.global.add.v4.f32 [%0], {%1, %2, %3, %4};"
                 :: "l"(up), "f"(v.x), "f"(v.y), "f"(v.z), "f"(v.w)
                 : "memory");
}

// ---------------------------------------------------------------------------
// Kernel 4: fp16 tensor-core GEMM + bias + relu.
// out[M,256] = relu(U[M,1024] @ Bt^T + bias)
// CTA tile 128x256 (full N), 512 threads (16 warps, warp tile 32x64),
// grid = 157 (~1 wave), BK=32, double-buffered, cp.async for B.
// ---------------------------------------------------------------------------
#define GBM 128
#define GBN 256
#define GBK 32
#define ASTR 40   // halves per row; 20 words -> conflict-free frag LDS
#define AS_HALVES (GBM * ASTR)      // 5120
#define BS_HALVES (GBN * ASTR)      // 10240
#define GEMM_SMEM_BYTES ((2 * AS_HALVES + 2 * BS_HALVES) * 2)   // 61440

__device__ __forceinline__ uint32_t smem_u32(const void* p) {
    return (uint32_t)__cvta_generic_to_shared(p);
}

__global__ __launch_bounds__(512, 1)
void gemm_tc_kernel(const __half* __restrict__ Bt,
                    const float* __restrict__ bias,
                    float* __restrict__ out, int M) {
    extern __shared__ __half smh[];
    __half* As = smh;                      // [2][GBM][ASTR]
    __half* Bs = smh + 2 * AS_HALVES;      // [2][GBN][ASTR]

    int tid  = threadIdx.x;
    int lane = tid & 31;
    int warp = tid >> 5;
    int wm = warp & 3;      // rows wm*32
    int wn = warp >> 2;     // cols wn*64
    int bm = blockIdx.x * GBM;

    // A staging: idx = tid, tid+512 -> row = idx>>3 (0..127), seg = idx&7
    int ar0 = tid >> 3;          // rows ar0, ar0+64
    int aseg = tid & 7;
    // B staging (cp.async): idx = tid, tid+512 -> row = idx>>2 (0..255), ch = idx&3
    int br0 = tid >> 2;          // rows br0, br0+128
    int bch = tid & 3;

    float4 aR[2];
    float acc[2][8][4];
    #pragma unroll
    for (int mf = 0; mf < 2; mf++)
        #pragma unroll
        for (int nf = 0; nf < 8; nf++)
            #pragma unroll
            for (int i = 0; i < 4; i++) acc[mf][nf][i] = 0.f;

    #define LOADA(k0)                                                           \
        do {                                                                    \
            aR[0] = *reinterpret_cast<const float4*>(                           \
                g_U + (size_t)(bm + ar0) * K_DIM + (k0) + aseg * 4);            \
            aR[1] = *reinterpret_cast<const float4*>(                           \
                g_U + (size_t)(bm + ar0 + 64) * K_DIM + (k0) + aseg * 4);       \
        } while (0)

    #define STOREA(buf)                                                         \
        do {                                                                    \
            _Pragma("unroll")                                                   \
            for (int i = 0; i < 2; i++) {                                       \
                __half2* d = reinterpret_cast<__half2*>(                        \
                    As + (buf) * AS_HALVES + (ar0 + i * 64) * ASTR + aseg * 4); \
                d[0] = __floats2half2_rn(aR[i].x, aR[i].y);                     \
                d[1] = __floats2half2_rn(aR[i].z, aR[i].w);                     \
            }                                                                   \
        } while (0)

    #define CPB(k0, buf)                                                        \
        do {                                                                    \
            _Pragma("unroll")                                                   \
            for (int i = 0; i < 2; i++) {                                       \
                uint32_t d = smem_u32(Bs + (buf) * BS_HALVES +                  \
                                      (br0 + i * 128) * ASTR + bch * 8);        \
                const __half* s = Bt + (size_t)(br0 + i * 128) * K_DIM +        \
                                  (k0) + bch * 8;                               \
                asm volatile("cp.async.cg.shared.global [%0], [%1], 16;"        \
                             :: "r"(d), "l"(s) : "memory");                     \
            }                                                                   \
            asm volatile("cp.async.commit_group;" ::: "memory");                \
        } while (0)

    // prologue: chunk 0 into buf 0; prefetch A regs for chunk 1
    LOADA(0);
    STOREA(0);
    CPB(0, 0);
    LOADA(GBK);
    asm volatile("cp.async.wait_group 0;" ::: "memory");
    __syncthreads();

    const int NITER = K_DIM / GBK;   // 32
    for (int it = 0; it < NITER; ++it) {
        int cur = it & 1;

        // stage next chunk (overlaps with MMA below via cp.async; STS is cheap)
        if (it + 1 < NITER) {
            STOREA(1 - cur);
            CPB((it + 1) * GBK, 1 - cur);
        }

        #pragma unroll
        for (int ks = 0; ks < 2; ks++) {          // two k16 steps per BK=32
            uint32_t afr[2][4], bfr[8][2];
            int ar_ = wm * 32 + (lane >> 2);
            int ak_ = ks * 16 + (lane & 3) * 2;
            #pragma unroll
            for (int mf = 0; mf < 2; mf++) {
                const __half* p = As + cur * AS_HALVES + (ar_ + mf * 16) * ASTR + ak_;
                afr[mf][0] = *reinterpret_cast<const uint32_t*>(p);
                afr[mf][1] = *reinterpret_cast<const uint32_t*>(p + 8 * ASTR);
                afr[mf][2] = *reinterpret_cast<const uint32_t*>(p + 8);
                afr[mf][3] = *reinterpret_cast<const uint32_t*>(p + 8 * ASTR + 8);
            }
            int bn_ = wn * 64 + (lane >> 2);
            #pragma unroll
            for (int nf = 0; nf < 8; nf++) {
                const __half* p = Bs + cur * BS_HALVES + (bn_ + nf * 8) * ASTR + ak_;
                bfr[nf][0] = *reinterpret_cast<const uint32_t*>(p);
                bfr[nf][1] = *reinterpret_cast<const uint32_t*>(p + 8);
            }
            #pragma unroll
            for (int mf = 0; mf < 2; mf++)
                #pragma unroll
                for (int nf = 0; nf < 8; nf++)
                    asm volatile(
                        "mma.sync.aligned.m16n8k16.row.col.f32.f16.f16.f32 "
                        "{%0,%1,%2,%3}, {%4,%5,%6,%7}, {%8,%9}, {%0,%1,%2,%3};"
                        : "+f"(acc[mf][nf][0]), "+f"(acc[mf][nf][1]),
                          "+f"(acc[mf][nf][2]), "+f"(acc[mf][nf][3])
                        : "r"(afr[mf][0]), "r"(afr[mf][1]),
                          "r"(afr[mf][2]), "r"(afr[mf][3]),
                          "r"(bfr[nf][0]), "r"(bfr[nf][1]));
        }

        // prefetch A regs for chunk it+2
        if (it + 2 < NITER) LOADA((it + 2) * GBK);

        if (it + 1 < NITER) {
            asm volatile("cp.async.wait_group 0;" ::: "memory");
            __syncthreads();
        }
    }

    // epilogue: + bias, relu
    #pragma unroll
    for (int mf = 0; mf < 2; mf++) {
        int row0 = bm + wm * 32 + mf * 16 + (lane >> 2);
        #pragma unroll
        for (int nf = 0; nf < 8; nf++) {
            int col = wn * 64 + nf * 8 + (lane & 3) * 2;
            float b0 = __ldg(bias + col);
            float b1 = __ldg(bias + col + 1);
            if (row0 < M) {
                float2 o;
                o.x = fmaxf(acc[mf][nf][0] + b0, 0.f);
                o.y = fmaxf(acc[mf][nf][1] + b1, 0.f);
                *reinterpret_cast<float2*>(out + (size_t)row0 * OUT_DIM + col) = o;
            }
            if (row0 + 8 < M) {
                float2 o;
                o.x = fmaxf(acc[mf][nf][2] + b0, 0.f);
                o.y = fmaxf(acc[mf][nf][3] + b1, 0.f);
                *reinterpret_cast<float2*>(out + (size_t)(row0 + 8) * OUT_DIM + col) = o;
            }
        }
    }
}

// ---------------------------------------------------------------------------
extern "C" void kernel_launch(void* const* d_in, const int* in_sizes, int n_in,
                              void* d_out, int out_size) {
    const float* h      = (const float*)d_in[0];
    const float* basis  = (const float*)d_in[1];
    const float* w_comp = (const float*)d_in[2];
    const float* bias   = (const float*)d_in[3];
    const int*   src    = (const int*)d_in[4];
    const int*   dst    = (const int*)d_in[5];
    const int*   etype  = (const int*)d_in[6];
    float* out = (float*)d_out;

    int N = in_sizes[0] / IN_DIM;   // 20000
    int E = in_sizes[4];            // 320000

    static cudaStream_t s1 = nullptr, s2 = nullptr;
    static cudaEvent_t e0 = nullptr, e1 = nullptr, e2 = nullptr;
    static bool init_done = false;
    if (!init_done) {
        cudaFuncSetAttribute(gemm_tc_kernel,
                             cudaFuncAttributeMaxDynamicSharedMemorySize,
                             GEMM_SMEM_BYTES);
        cudaStreamCreateWithFlags(&s1, cudaStreamNonBlocking);
        cudaStreamCreateWithFlags(&s2, cudaStreamNonBlocking);
        cudaEventCreateWithFlags(&e0, cudaEventDisableTiming);
        cudaEventCreateWithFlags(&e1, cudaEventDisableTiming);
        cudaEventCreateWithFlags(&e2, cudaEventDisableTiming);
        init_done = true;
    }

    void* uptr = nullptr;
    cudaGetSymbolAddress(&uptr, g_U);
    __half* btp = nullptr;
    cudaGetSymbolAddress((void**)&btp, g_Bt);

    // Fork side streams off the main (capture) stream.
    cudaEventRecord(e0, 0);
    cudaStreamWaitEvent(s1, e0, 0);
    cudaStreamWaitEvent(s2, e0, 0);

    // launch call #1: memset U on s1 (parallel with fold)
    cudaMemsetAsync(uptr, 0, (size_t)M_PAD * K_DIM * sizeof(float), s1);
    cudaEventRecord(e1, s1);

    // #2: fold on main stream
    fold_kernel<<<(N * 32 + 255) / 256, 256>>>(h, w_comp, N);

    // #3: transpose on s2 (parallel)
    transpose_kernel<<<dim3(32, 8), dim3(32, 8), 0, s2>>>(basis);
    cudaEventRecord(e2, s2);

    // join: scatter needs memset+fold; gemm additionally needs transpose
    cudaStreamWaitEvent(0, e1, 0);
    cudaStreamWaitEvent(0, e2, 0);

    // #4: scatter
    scatter_kernel<<<(E * 32 + 255) / 256, 256>>>(src, dst, etype, E);

    // #5: GEMM (ncu capture point)
    gemm_tc_kernel<<<M_PAD / GBM, 512, GEMM_SMEM_BYTES>>>(btp, bias, out, N);
}

// round 6
// speedup vs baseline: 1.4854x; 1.4854x over previous
#include <cuda_runtime.h>
#include <cuda_fp16.h>
#include <cstdint>

#define N_NODES   20000
#define M_PAD     20096      // 157 * 128
#define IN_DIM    256
#define OUT_DIM   256
#define FOLD_DIM  128        // 32 q-groups * 4 bases
#define K_DIM     1024       // 8 relations * 128

// Scratch (static device globals — no allocation allowed)
__device__ __half g_hf[N_NODES * FOLD_DIM];        // folded h  [N, 128] fp16
__device__ __half g_U [(size_t)M_PAD * K_DIM];     // aggregated [M_PAD, 1024] fp16
__device__ __half g_Bt[(size_t)OUT_DIM * K_DIM];   // basis^T, K-major, fp16

// ---------------------------------------------------------------------------
// Kernel 1: fold h with w_comp.  hf[n, q*4+b] = sum_p h[n, q*8+p] * w_comp[p,b]
// Output fp16.
// ---------------------------------------------------------------------------
__global__ void fold_kernel(const float* __restrict__ h,
                            const float* __restrict__ w_comp, int N) {
    __shared__ float wc[32];
    if (threadIdx.x < 32) wc[threadIdx.x] = w_comp[threadIdx.x];
    __syncthreads();

    int idx = blockIdx.x * blockDim.x + threadIdx.x;
    if (idx >= N * 32) return;
    int n = idx >> 5;
    int q = idx & 31;

    const float4* hp = reinterpret_cast<const float4*>(h + (size_t)n * IN_DIM + q * 8);
    float4 h0 = hp[0];
    float4 h1 = hp[1];
    float hv[8] = {h0.x, h0.y, h0.z, h0.w, h1.x, h1.y, h1.z, h1.w};

    float o[4];
    #pragma unroll
    for (int b = 0; b < 4; b++) {
        float s = 0.f;
        #pragma unroll
        for (int p = 0; p < 8; p++) s += hv[p] * wc[p * 4 + b];
        o[b] = s;
    }
    __half2 p0 = __floats2half2_rn(o[0], o[1]);
    __half2 p1 = __floats2half2_rn(o[2], o[3]);
    __half2* d = reinterpret_cast<__half2*>(g_hf + (size_t)n * FOLD_DIM + q * 4);
    d[0] = p0;
    d[1] = p1;
}

// ---------------------------------------------------------------------------
// Kernel 2: transpose basis [1024,256] -> g_Bt [256,1024] (K-major) as fp16.
// ---------------------------------------------------------------------------
__global__ void transpose_kernel(const float* __restrict__ basis) {
    __shared__ float t[32][33];
    int bx = blockIdx.x;   // k tile (32)
    int by = blockIdx.y;   // n tile (8)
    int x = threadIdx.x;   // 0..31
    int y = threadIdx.y;   // 0..7
    #pragma unroll
    for (int i = 0; i < 4; i++)
        t[y + i * 8][x] = basis[(size_t)(bx * 32 + y + i * 8) * OUT_DIM + by * 32 + x];
    __syncthreads();
    #pragma unroll
    for (int i = 0; i < 4; i++)
        g_Bt[(size_t)(by * 32 + y + i * 8) * K_DIM + bx * 32 + x] =
            __float2half_rn(t[x][y + i * 8]);
}

// ---------------------------------------------------------------------------
// Kernel 3: edge scatter, fp16. Half-warp (16 lanes) per edge.
// U[dst, etype*128 + j] += hf[src, j]   via red.global.add.noftz.v4.f16x2
// ---------------------------------------------------------------------------
__global__ void scatter_kernel(const int* __restrict__ src,
                               const int* __restrict__ dst,
                               const int* __restrict__ etype, int E) {
    int warp = (blockIdx.x * blockDim.x + threadIdx.x) >> 5;
    int lane = threadIdx.x & 31;
    int e = warp * 2 + (lane >> 4);      // 2 edges per warp
    int l = lane & 15;                   // 16 lanes cover 128 halves
    if (e >= E) return;

    int s = __ldg(src + e);
    int d = __ldg(dst + e);
    int r = __ldg(etype + e);

    uint4 v = *reinterpret_cast<const uint4*>(g_hf + (size_t)s * FOLD_DIM + l * 8);
    __half* up = g_U + (size_t)d * K_DIM + r * FOLD_DIM + l * 8;
    asm volatile("red.global.add.noftz.v4.f16x2 [%0], {%1, %2, %3, %4};"
                 :: "l"(up), "r"(v.x), "r"(v.y), "r"(v.z), "r"(v.w)
                 : "memory");
}

// ---------------------------------------------------------------------------
// Kernel 4: fp16 tensor-core GEMM + bias + relu.
// out[M,256] = relu(U[M,1024] @ Bt^T + bias)
// CTA 128x128, 256 threads (8 warps, warp tile 32x64), grid 157x2,
// 4-stage cp.async pipeline for BOTH operands, 2 CTAs/SM.
// ---------------------------------------------------------------------------
#define GBM 128
#define GBN 128
#define GBK 32
#define STAGES 4
#define ASTR 40   // halves per row; conflict-free fragment LDS (verified R4)
#define TILE_HALVES (GBM * ASTR)                         // 5120 per operand/stage
#define GEMM_SMEM_BYTES (2 * STAGES * TILE_HALVES * 2)   // 81920 B

__device__ __forceinline__ uint32_t smem_u32(const void* p) {
    return (uint32_t)__cvta_generic_to_shared(p);
}

__global__ __launch_bounds__(256, 2)
void gemm_tc_kernel(const __half* __restrict__ Bt,
                    const float* __restrict__ bias,
                    float* __restrict__ out, int M) {
    extern __shared__ __half smh[];
    __half* As = smh;                         // [STAGES][128][ASTR]
    __half* Bs = smh + STAGES * TILE_HALVES;  // [STAGES][128][ASTR]

    int tid  = threadIdx.x;
    int lane = tid & 31;
    int warp = tid >> 5;
    int wm = warp >> 1;     // rows wm*32
    int wn = warp & 1;      // cols wn*64
    int bm = blockIdx.x * GBM;
    int bn = blockIdx.y * GBN;

    // cp.async staging: idx = tid + i*256 (0..511); row = idx>>2, seg = idx&3
    int srow = tid >> 2;         // rows srow, srow+64
    int sseg = tid & 3;          // 8-half (16B) segment

    float acc[2][8][4];
    #pragma unroll
    for (int mf = 0; mf < 2; mf++)
        #pragma unroll
        for (int nf = 0; nf < 8; nf++)
            #pragma unroll
            for (int i = 0; i < 4; i++) acc[mf][nf][i] = 0.f;

    #define ISSUE_STAGE(stg, k0)                                                  \
        do {                                                                      \
            _Pragma("unroll")                                                     \
            for (int i = 0; i < 2; i++) {                                         \
                int row = srow + i * 64;                                          \
                uint32_t da = smem_u32(As + (stg) * TILE_HALVES + row * ASTR + sseg * 8); \
                const __half* sa = g_U + (size_t)(bm + row) * K_DIM + (k0) + sseg * 8;    \
                asm volatile("cp.async.cg.shared.global [%0], [%1], 16;"          \
                             :: "r"(da), "l"(sa) : "memory");                     \
                uint32_t db = smem_u32(Bs + (stg) * TILE_HALVES + row * ASTR + sseg * 8); \
                const __half* sb = Bt + (size_t)(bn + row) * K_DIM + (k0) + sseg * 8;     \
                asm volatile("cp.async.cg.shared.global [%0], [%1], 16;"          \
                             :: "r"(db), "l"(sb) : "memory");                     \
            }                                                                     \
            asm volatile("cp.async.commit_group;" ::: "memory");                  \
        } while (0)

    // prologue: issue stages 0..2
    ISSUE_STAGE(0, 0);
    ISSUE_STAGE(1, GBK);
    ISSUE_STAGE(2, 2 * GBK);

    const int NITER = K_DIM / GBK;   // 32
    for (int it = 0; it < NITER; ++it) {
        int cur = it & (STAGES - 1);

        asm volatile("cp.async.wait_group %0;" :: "n"(STAGES - 2) : "memory");
        __syncthreads();

        // issue stage it+3 into the buffer freed at iter it-1
        if (it + 3 < NITER) ISSUE_STAGE((it + 3) & (STAGES - 1), (it + 3) * GBK);

        const __half* as = As + cur * TILE_HALVES;
        const __half* bs = Bs + cur * TILE_HALVES;

        #pragma unroll
        for (int ks = 0; ks < 2; ks++) {          // two k16 steps per BK=32
            uint32_t afr[2][4], bfr[8][2];
            int ar_ = wm * 32 + (lane >> 2);
            int ak_ = ks * 16 + (lane & 3) * 2;
            #pragma unroll
            for (int mf = 0; mf < 2; mf++) {
                const __half* p = as + (ar_ + mf * 16) * ASTR + ak_;
                afr[mf][0] = *reinterpret_cast<const uint32_t*>(p);
                afr[mf][1] = *reinterpret_cast<const uint32_t*>(p + 8 * ASTR);
                afr[mf][2] = *reinterpret_cast<const uint32_t*>(p + 8);
                afr[mf][3] = *reinterpret_cast<const uint32_t*>(p + 8 * ASTR + 8);
            }
            int bn_ = wn * 64 + (lane >> 2);
            #pragma unroll
            for (int nf = 0; nf < 8; nf++) {
                const __half* p = bs + (bn_ + nf * 8) * ASTR + ak_;
                bfr[nf][0] = *reinterpret_cast<const uint32_t*>(p);
                bfr[nf][1] = *reinterpret_cast<const uint32_t*>(p + 8);
            }
            #pragma unroll
            for (int mf = 0; mf < 2; mf++)
                #pragma unroll
                for (int nf = 0; nf < 8; nf++)
                    asm volatile(
                        "mma.sync.aligned.m16n8k16.row.col.f32.f16.f16.f32 "
                        "{%0,%1,%2,%3}, {%4,%5,%6,%7}, {%8,%9}, {%0,%1,%2,%3};"
                        : "+f"(acc[mf][nf][0]), "+f"(acc[mf][nf][1]),
                          "+f"(acc[mf][nf][2]), "+f"(acc[mf][nf][3])
                        : "r"(afr[mf][0]), "r"(afr[mf][1]),
                          "r"(afr[mf][2]), "r"(afr[mf][3]),
                          "r"(bfr[nf][0]), "r"(bfr[nf][1]));
        }
    }

    // epilogue: + bias, relu
    #pragma unroll
    for (int mf = 0; mf < 2; mf++) {
        int row0 = bm + wm * 32 + mf * 16 + (lane >> 2);
        #pragma unroll
        for (int nf = 0; nf < 8; nf++) {
            int col = bn + wn * 64 + nf * 8 + (lane & 3) * 2;
            float b0 = __ldg(bias + col);
            float b1 = __ldg(bias + col + 1);
            if (row0 < M) {
                float2 o;
                o.x = fmaxf(acc[mf][nf][0] + b0, 0.f);
                o.y = fmaxf(acc[mf][nf][1] + b1, 0.f);
                *reinterpret_cast<float2*>(out + (size_t)row0 * OUT_DIM + col) = o;
            }
            if (row0 + 8 < M) {
                float2 o;
                o.x = fmaxf(acc[mf][nf][2] + b0, 0.f);
                o.y = fmaxf(acc[mf][nf][3] + b1, 0.f);
                *reinterpret_cast<float2*>(out + (size_t)(row0 + 8) * OUT_DIM + col) = o;
            }
        }
    }
}

// ---------------------------------------------------------------------------
extern "C" void kernel_launch(void* const* d_in, const int* in_sizes, int n_in,
                              void* d_out, int out_size) {
    const float* h      = (const float*)d_in[0];
    const float* basis  = (const float*)d_in[1];
    const float* w_comp = (const float*)d_in[2];
    const float* bias   = (const float*)d_in[3];
    const int*   src    = (const int*)d_in[4];
    const int*   dst    = (const int*)d_in[5];
    const int*   etype  = (const int*)d_in[6];
    float* out = (float*)d_out;

    int N = in_sizes[0] / IN_DIM;   // 20000
    int E = in_sizes[4];            // 320000

    static cudaStream_t s1 = nullptr;
    static cudaEvent_t e0 = nullptr, e1 = nullptr;
    static bool init_done = false;
    if (!init_done) {
        cudaFuncSetAttribute(gemm_tc_kernel,
                             cudaFuncAttributeMaxDynamicSharedMemorySize,
                             GEMM_SMEM_BYTES);
        cudaStreamCreateWithFlags(&s1, cudaStreamNonBlocking);
        cudaEventCreateWithFlags(&e0, cudaEventDisableTiming);
        cudaEventCreateWithFlags(&e1, cudaEventDisableTiming);
        init_done = true;
    }

    void* uptr = nullptr;
    cudaGetSymbolAddress(&uptr, g_U);
    __half* btp = nullptr;
    cudaGetSymbolAddress((void**)&btp, g_Bt);

    // fork: memset U on s1, parallel with fold+transpose on main
    cudaEventRecord(e0, 0);
    cudaStreamWaitEvent(s1, e0, 0);
    cudaMemsetAsync(uptr, 0, (size_t)M_PAD * K_DIM * sizeof(__half), s1);  // #1
    cudaEventRecord(e1, s1);

    fold_kernel<<<(N * 32 + 255) / 256, 256>>>(h, w_comp, N);              // #2
    transpose_kernel<<<dim3(32, 8), dim3(32, 8)>>>(basis);                 // #3

    cudaStreamWaitEvent(0, e1, 0);   // join before scatter

    scatter_kernel<<<(E + 15) / 16, 256>>>(src, dst, etype, E);            // #4

    dim3 grid(M_PAD / GBM, OUT_DIM / GBN);   // 157 x 2
    gemm_tc_kernel<<<grid, 256, GEMM_SMEM_BYTES>>>(btp, bias, out, N);     // #5 (ncu)
}

// round 7
// speedup vs baseline: 1.7161x; 1.1553x over previous
#include <cuda_runtime.h>
#include <cuda_fp16.h>
#include <cstdint>

#define N_NODES   20000
#define M_PAD     20096      // 157 * 128
#define IN_DIM    256
#define OUT_DIM   256
#define FOLD_DIM  128        // 32 q-groups * 4 bases
#define K_DIM     1024       // 8 relations * 128

// Scratch (static device globals — no allocation allowed)
__device__ __half g_hf[N_NODES * FOLD_DIM];        // folded h  [N, 128] fp16
__device__ __half g_U [(size_t)M_PAD * K_DIM];     // aggregated [M_PAD, 1024] fp16
__device__ __half g_Bt[(size_t)OUT_DIM * K_DIM];   // basis^T, K-major, fp16

// ---------------------------------------------------------------------------
// Kernel 1: fold h with w_comp.  hf[n, q*4+b] = sum_p h[n, q*8+p] * w_comp[p,b]
// ---------------------------------------------------------------------------
__global__ void fold_kernel(const float* __restrict__ h,
                            const float* __restrict__ w_comp, int N) {
    __shared__ float wc[32];
    if (threadIdx.x < 32) wc[threadIdx.x] = w_comp[threadIdx.x];
    __syncthreads();

    int idx = blockIdx.x * blockDim.x + threadIdx.x;
    if (idx >= N * 32) return;
    int n = idx >> 5;
    int q = idx & 31;

    const float4* hp = reinterpret_cast<const float4*>(h + (size_t)n * IN_DIM + q * 8);
    float4 h0 = hp[0];
    float4 h1 = hp[1];
    float hv[8] = {h0.x, h0.y, h0.z, h0.w, h1.x, h1.y, h1.z, h1.w};

    float o[4];
    #pragma unroll
    for (int b = 0; b < 4; b++) {
        float s = 0.f;
        #pragma unroll
        for (int p = 0; p < 8; p++) s += hv[p] * wc[p * 4 + b];
        o[b] = s;
    }
    __half2 p0 = __floats2half2_rn(o[0], o[1]);
    __half2 p1 = __floats2half2_rn(o[2], o[3]);
    __half2* d = reinterpret_cast<__half2*>(g_hf + (size_t)n * FOLD_DIM + q * 4);
    d[0] = p0;
    d[1] = p1;
}

// ---------------------------------------------------------------------------
// Kernel 2: transpose basis [1024,256] -> g_Bt [256,1024] (K-major) as fp16.
// ---------------------------------------------------------------------------
__global__ void transpose_kernel(const float* __restrict__ basis) {
    __shared__ float t[32][33];
    int bx = blockIdx.x;
    int by = blockIdx.y;
    int x = threadIdx.x;
    int y = threadIdx.y;
    #pragma unroll
    for (int i = 0; i < 4; i++)
        t[y + i * 8][x] = basis[(size_t)(bx * 32 + y + i * 8) * OUT_DIM + by * 32 + x];
    __syncthreads();
    #pragma unroll
    for (int i = 0; i < 4; i++)
        g_Bt[(size_t)(by * 32 + y + i * 8) * K_DIM + bx * 32 + x] =
            __float2half_rn(t[x][y + i * 8]);
}

// ---------------------------------------------------------------------------
// Kernel 3: edge scatter, fp16. 16 lanes per edge, red.add.noftz.v4.f16x2
// ---------------------------------------------------------------------------
__global__ void scatter_kernel(const int* __restrict__ src,
                               const int* __restrict__ dst,
                               const int* __restrict__ etype, int E) {
    int warp = (blockIdx.x * blockDim.x + threadIdx.x) >> 5;
    int lane = threadIdx.x & 31;
    int e = warp * 2 + (lane >> 4);
    int l = lane & 15;
    if (e >= E) return;

    int s = __ldg(src + e);
    int d = __ldg(dst + e);
    int r = __ldg(etype + e);

    uint4 v = *reinterpret_cast<const uint4*>(g_hf + (size_t)s * FOLD_DIM + l * 8);
    __half* up = g_U + (size_t)d * K_DIM + r * FOLD_DIM + l * 8;
    asm volatile("red.global.add.noftz.v4.f16x2 [%0], {%1, %2, %3, %4};"
                 :: "l"(up), "r"(v.x), "r"(v.y), "r"(v.z), "r"(v.w)
                 : "memory");
}

// ---------------------------------------------------------------------------
// Kernel 4: fp16 tensor-core GEMM + bias + relu.
// out[M,256] = relu(U[M,1024] @ Bt^T + bias)
// CTA 128x128, 256 threads (8 warps, warp tile 32x64), grid 157x2, 2 CTAs/SM.
// BK=64, 3-stage cp.async pipeline, SW128-swizzled smem, ldmatrix fragments.
// ---------------------------------------------------------------------------
#define GBM 128
#define GBN 128
#define GBK 64
#define STAGES 3
#define STAGE_BYTES (GBM * 128)                       // 16 KB per operand-stage
#define GEMM_SMEM_BYTES (2 * STAGES * STAGE_BYTES)    // 98304 B

#define SWZ(o) ((o) ^ (((o) >> 3) & 0x70))

__device__ __forceinline__ uint32_t smem_u32(const void* p) {
    return (uint32_t)__cvta_generic_to_shared(p);
}

__global__ __launch_bounds__(256, 2)
void gemm_tc_kernel(const __half* __restrict__ Bt,
                    const float* __restrict__ bias,
                    float* __restrict__ out, int M) {
    extern __shared__ char smem[];
    char* As = smem;                            // [STAGES][128 rows][128 B] swizzled
    char* Bs = smem + STAGES * STAGE_BYTES;     // [STAGES][128 rows][128 B] swizzled

    int tid  = threadIdx.x;
    int lane = tid & 31;
    int warp = tid >> 5;
    int wm = warp >> 1;     // rows wm*32
    int wn = warp & 1;      // cols wn*64
    int bm = blockIdx.x * GBM;
    int bn = blockIdx.y * GBN;

    float acc[2][8][4];
    #pragma unroll
    for (int mf = 0; mf < 2; mf++)
        #pragma unroll
        for (int nf = 0; nf < 8; nf++)
            #pragma unroll
            for (int i = 0; i < 4; i++) acc[mf][nf][i] = 0.f;

    // cp.async staging: 1024 16B-segments per operand-stage; 4 per thread
    #define ISSUE_STAGE(stg, k0)                                                    \
        do {                                                                        \
            _Pragma("unroll")                                                       \
            for (int i = 0; i < 4; i++) {                                           \
                int idx = tid + i * 256;                                            \
                int row = idx >> 3;                                                 \
                int seg = idx & 7;                                                  \
                int so  = SWZ(row * 128 + seg * 16);                                \
                uint32_t da = smem_u32(As + (stg) * STAGE_BYTES + so);              \
                const __half* sa = g_U + (size_t)(bm + row) * K_DIM + (k0) + seg * 8; \
                asm volatile("cp.async.cg.shared.global [%0], [%1], 16;"            \
                             :: "r"(da), "l"(sa) : "memory");                       \
                uint32_t db = smem_u32(Bs + (stg) * STAGE_BYTES + so);              \
                const __half* sb = Bt + (size_t)(bn + row) * K_DIM + (k0) + seg * 8;  \
                asm volatile("cp.async.cg.shared.global [%0], [%1], 16;"            \
                             :: "r"(db), "l"(sb) : "memory");                       \
            }                                                                       \
            asm volatile("cp.async.commit_group;" ::: "memory");                    \
        } while (0)

    // prologue: stages 0,1
    ISSUE_STAGE(0, 0);
    ISSUE_STAGE(1, GBK);

    // ldmatrix lane geometry (same for A and B)
    int frow = lane & 15;          // row within 16-row block
    int fkb  = (lane >> 4) * 16;   // 0 or 16 bytes (k halves 0-7 / 8-15)

    const int NITER = K_DIM / GBK;   // 16
    for (int it = 0; it < NITER; ++it) {
        int cur = it % STAGES;

        asm volatile("cp.async.wait_group %0;" :: "n"(1) : "memory");
        __syncthreads();

        if (it + 2 < NITER) ISSUE_STAGE((it + 2) % STAGES, (it + 2) * GBK);

        const char* as = As + cur * STAGE_BYTES;
        const char* bs = Bs + cur * STAGE_BYTES;

        #pragma unroll
        for (int ks = 0; ks < 4; ks++) {          // four k16 steps per BK=64
            int kb = ks * 32 + fkb;               // k byte offset of this thread's 16B

            uint32_t afr[2][4];
            #pragma unroll
            for (int mf = 0; mf < 2; mf++) {
                uint32_t addr = smem_u32(
                    as + SWZ((wm * 32 + mf * 16 + frow) * 128 + kb));
                asm volatile(
                    "ldmatrix.sync.aligned.m8n8.x4.shared.b16 {%0,%1,%2,%3}, [%4];"
                    : "=r"(afr[mf][0]), "=r"(afr[mf][1]),
                      "=r"(afr[mf][2]), "=r"(afr[mf][3])
                    : "r"(addr));
            }
            uint32_t bfr[8][2];
            #pragma unroll
            for (int p = 0; p < 4; p++) {         // nf pair {2p, 2p+1}
                uint32_t r0, r1, r2, r3;
                uint32_t addr = smem_u32(
                    bs + SWZ((wn * 64 + p * 16 + frow) * 128 + kb));
                asm volatile(
                    "ldmatrix.sync.aligned.m8n8.x4.shared.b16 {%0,%1,%2,%3}, [%4];"
                    : "=r"(r0), "=r"(r1), "=r"(r2), "=r"(r3)
                    : "r"(addr));
                bfr[2 * p][0] = r0; bfr[2 * p + 1][0] = r1;
                bfr[2 * p][1] = r2; bfr[2 * p + 1][1] = r3;
            }
            #pragma unroll
            for (int mf = 0; mf < 2; mf++)
                #pragma unroll
                for (int nf = 0; nf < 8; nf++)
                    asm volatile(
                        "mma.sync.aligned.m16n8k16.row.col.f32.f16.f16.f32 "
                        "{%0,%1,%2,%3}, {%4,%5,%6,%7}, {%8,%9}, {%0,%1,%2,%3};"
                        : "+f"(acc[mf][nf][0]), "+f"(acc[mf][nf][1]),
                          "+f"(acc[mf][nf][2]), "+f"(acc[mf][nf][3])
                        : "r"(afr[mf][0]), "r"(afr[mf][1]),
                          "r"(afr[mf][2]), "r"(afr[mf][3]),
                          "r"(bfr[nf][0]), "r"(bfr[nf][1]));
        }
    }

    // epilogue: + bias, relu
    #pragma unroll
    for (int mf = 0; mf < 2; mf++) {
        int row0 = bm + wm * 32 + mf * 16 + (lane >> 2);
        #pragma unroll
        for (int nf = 0; nf < 8; nf++) {
            int col = bn + wn * 64 + nf * 8 + (lane & 3) * 2;
            float b0 = __ldg(bias + col);
            float b1 = __ldg(bias + col + 1);
            if (row0 < M) {
                float2 o;
                o.x = fmaxf(acc[mf][nf][0] + b0, 0.f);
                o.y = fmaxf(acc[mf][nf][1] + b1, 0.f);
                *reinterpret_cast<float2*>(out + (size_t)row0 * OUT_DIM + col) = o;
            }
            if (row0 + 8 < M) {
                float2 o;
                o.x = fmaxf(acc[mf][nf][2] + b0, 0.f);
                o.y = fmaxf(acc[mf][nf][3] + b1, 0.f);
                *reinterpret_cast<float2*>(out + (size_t)(row0 + 8) * OUT_DIM + col) = o;
            }
        }
    }
}

// ---------------------------------------------------------------------------
extern "C" void kernel_launch(void* const* d_in, const int* in_sizes, int n_in,
                              void* d_out, int out_size) {
    const float* h      = (const float*)d_in[0];
    const float* basis  = (const float*)d_in[1];
    const float* w_comp = (const float*)d_in[2];
    const float* bias   = (const float*)d_in[3];
    const int*   src    = (const int*)d_in[4];
    const int*   dst    = (const int*)d_in[5];
    const int*   etype  = (const int*)d_in[6];
    float* out = (float*)d_out;

    int N = in_sizes[0] / IN_DIM;   // 20000
    int E = in_sizes[4];            // 320000

    static cudaStream_t s1 = nullptr;
    static cudaEvent_t e0 = nullptr, e1 = nullptr;
    static bool init_done = false;
    if (!init_done) {
        cudaFuncSetAttribute(gemm_tc_kernel,
                             cudaFuncAttributeMaxDynamicSharedMemorySize,
                             GEMM_SMEM_BYTES);
        cudaStreamCreateWithFlags(&s1, cudaStreamNonBlocking);
        cudaEventCreateWithFlags(&e0, cudaEventDisableTiming);
        cudaEventCreateWithFlags(&e1, cudaEventDisableTiming);
        init_done = true;
    }

    void* uptr = nullptr;
    cudaGetSymbolAddress(&uptr, g_U);
    __half* btp = nullptr;
    cudaGetSymbolAddress((void**)&btp, g_Bt);

    // fork: memset U on s1, parallel with fold+transpose on main
    cudaEventRecord(e0, 0);
    cudaStreamWaitEvent(s1, e0, 0);
    cudaMemsetAsync(uptr, 0, (size_t)M_PAD * K_DIM * sizeof(__half), s1);  // #1
    cudaEventRecord(e1, s1);

    fold_kernel<<<(N * 32 + 255) / 256, 256>>>(h, w_comp, N);              // #2
    transpose_kernel<<<dim3(32, 8), dim3(32, 8)>>>(basis);                 // #3

    cudaStreamWaitEvent(0, e1, 0);   // join before scatter

    scatter_kernel<<<(E + 15) / 16, 256>>>(src, dst, etype, E);            // #4

    dim3 grid(M_PAD / GBM, OUT_DIM / GBN);   // 157 x 2
    gemm_tc_kernel<<<grid, 256, GEMM_SMEM_BYTES>>>(btp, bias, out, N);     // #5 (ncu)
}

// round 8
// speedup vs baseline: 1.7676x; 1.0300x over previous
#include <cuda_runtime.h>
#include <cuda_fp16.h>
#include <cstdint>

#define N_NODES   20000
#define M_PAD     20096      // 157 * 128
#define IN_DIM    256
#define OUT_DIM   256
#define FOLD_DIM  128        // 32 q-groups * 4 bases
#define K_DIM     1024       // 8 relations * 128

// Scratch (static device globals — no allocation allowed)
__device__ __half g_hf[N_NODES * FOLD_DIM];        // folded h  [N, 128] fp16
__device__ __half g_U [(size_t)M_PAD * K_DIM];     // aggregated [M_PAD, 1024] fp16
__device__ __half g_Bt[(size_t)OUT_DIM * K_DIM];   // basis^T, K-major, fp16

// ---------------------------------------------------------------------------
// Kernel 1: fold h with w_comp.  hf[n, q*4+b] = sum_p h[n, q*8+p] * w_comp[p,b]
// ---------------------------------------------------------------------------
__global__ void fold_kernel(const float* __restrict__ h,
                            const float* __restrict__ w_comp, int N) {
    __shared__ float wc[32];
    if (threadIdx.x < 32) wc[threadIdx.x] = w_comp[threadIdx.x];
    __syncthreads();

    int idx = blockIdx.x * blockDim.x + threadIdx.x;
    if (idx >= N * 32) return;
    int n = idx >> 5;
    int q = idx & 31;

    const float4* hp = reinterpret_cast<const float4*>(h + (size_t)n * IN_DIM + q * 8);
    float4 h0 = hp[0];
    float4 h1 = hp[1];
    float hv[8] = {h0.x, h0.y, h0.z, h0.w, h1.x, h1.y, h1.z, h1.w};

    float o[4];
    #pragma unroll
    for (int b = 0; b < 4; b++) {
        float s = 0.f;
        #pragma unroll
        for (int p = 0; p < 8; p++) s += hv[p] * wc[p * 4 + b];
        o[b] = s;
    }
    __half2 p0 = __floats2half2_rn(o[0], o[1]);
    __half2 p1 = __floats2half2_rn(o[2], o[3]);
    __half2* d = reinterpret_cast<__half2*>(g_hf + (size_t)n * FOLD_DIM + q * 4);
    d[0] = p0;
    d[1] = p1;
}

// ---------------------------------------------------------------------------
// Kernel 2: transpose basis [1024,256] -> g_Bt [256,1024] (K-major) as fp16.
// ---------------------------------------------------------------------------
__global__ void transpose_kernel(const float* __restrict__ basis) {
    __shared__ float t[32][33];
    int bx = blockIdx.x;
    int by = blockIdx.y;
    int x = threadIdx.x;
    int y = threadIdx.y;
    #pragma unroll
    for (int i = 0; i < 4; i++)
        t[y + i * 8][x] = basis[(size_t)(bx * 32 + y + i * 8) * OUT_DIM + by * 32 + x];
    __syncthreads();
    #pragma unroll
    for (int i = 0; i < 4; i++)
        g_Bt[(size_t)(by * 32 + y + i * 8) * K_DIM + bx * 32 + x] =
            __float2half_rn(t[x][y + i * 8]);
}

// ---------------------------------------------------------------------------
// Kernel 3: edge scatter, fp16. 16 lanes per edge, red.add.noftz.v4.f16x2
// ---------------------------------------------------------------------------
__global__ void scatter_kernel(const int* __restrict__ src,
                               const int* __restrict__ dst,
                               const int* __restrict__ etype, int E) {
    int warp = (blockIdx.x * blockDim.x + threadIdx.x) >> 5;
    int lane = threadIdx.x & 31;
    int e = warp * 2 + (lane >> 4);
    int l = lane & 15;
    if (e >= E) return;

    int s = __ldg(src + e);
    int d = __ldg(dst + e);
    int r = __ldg(etype + e);

    uint4 v = *reinterpret_cast<const uint4*>(g_hf + (size_t)s * FOLD_DIM + l * 8);
    __half* up = g_U + (size_t)d * K_DIM + r * FOLD_DIM + l * 8;
    asm volatile("red.global.add.noftz.v4.f16x2 [%0], {%1, %2, %3, %4};"
                 :: "l"(up), "r"(v.x), "r"(v.y), "r"(v.z), "r"(v.w)
                 : "memory");
}

// ---------------------------------------------------------------------------
// Kernel 4: fp16 tensor-core GEMM + bias + relu.
// out[M,256] = relu(U[M,1024] @ Bt^T + bias)
// CTA 128x128, 256 threads (8 warps, warp tile 32x64), 2 CTAs/SM.
// BK=64, 3-stage cp.async pipeline, SW128 smem, ldmatrix fragments with
// intra-iteration fragment double-buffering (LDSM(ks+1) overlaps MMA(ks)).
// ---------------------------------------------------------------------------
#define GBM 128
#define GBN 128
#define GBK 64
#define STAGES 3
#define STAGE_BYTES (GBM * 128)                       // 16 KB per operand-stage
#define GEMM_SMEM_BYTES (2 * STAGES * STAGE_BYTES)    // 98304 B

#define SWZ(o) ((o) ^ (((o) >> 3) & 0x70))

__device__ __forceinline__ uint32_t smem_u32(const void* p) {
    return (uint32_t)__cvta_generic_to_shared(p);
}

__global__ __launch_bounds__(256, 2)
void gemm_tc_kernel(const __half* __restrict__ Bt,
                    const float* __restrict__ bias,
                    float* __restrict__ out, int M) {
    extern __shared__ char smem[];
    char* As = smem;                            // [STAGES][128 rows][128 B] swizzled
    char* Bs = smem + STAGES * STAGE_BYTES;     // [STAGES][128 rows][128 B] swizzled

    int tid  = threadIdx.x;
    int lane = tid & 31;
    int warp = tid >> 5;
    int wm = warp >> 1;     // rows wm*32
    int wn = warp & 1;      // cols wn*64
    int bm = blockIdx.x * GBM;
    int bn = blockIdx.y * GBN;

    float acc[2][8][4];
    #pragma unroll
    for (int mf = 0; mf < 2; mf++)
        #pragma unroll
        for (int nf = 0; nf < 8; nf++)
            #pragma unroll
            for (int i = 0; i < 4; i++) acc[mf][nf][i] = 0.f;

    // cp.async staging: 1024 16B-segments per operand-stage; 4 per thread
    #define ISSUE_STAGE(stg, k0)                                                    \
        do {                                                                        \
            _Pragma("unroll")                                                       \
            for (int i = 0; i < 4; i++) {                                           \
                int idx = tid + i * 256;                                            \
                int row = idx >> 3;                                                 \
                int seg = idx & 7;                                                  \
                int so  = SWZ(row * 128 + seg * 16);                                \
                uint32_t da = smem_u32(As + (stg) * STAGE_BYTES + so);              \
                const __half* sa = g_U + (size_t)(bm + row) * K_DIM + (k0) + seg * 8; \
                asm volatile("cp.async.cg.shared.global [%0], [%1], 16;"            \
                             :: "r"(da), "l"(sa) : "memory");                       \
                uint32_t db = smem_u32(Bs + (stg) * STAGE_BYTES + so);              \
                const __half* sb = Bt + (size_t)(bn + row) * K_DIM + (k0) + seg * 8;  \
                asm volatile("cp.async.cg.shared.global [%0], [%1], 16;"            \
                             :: "r"(db), "l"(sb) : "memory");                       \
            }                                                                       \
            asm volatile("cp.async.commit_group;" ::: "memory");                    \
        } while (0)

    // prologue: stages 0,1
    ISSUE_STAGE(0, 0);
    ISSUE_STAGE(1, GBK);

    // ldmatrix lane geometry (same for A and B)
    int frow = lane & 15;          // row within 16-row block
    int fkb  = (lane >> 4) * 16;   // 0 or 16 bytes (k halves 0-7 / 8-15)

    // double-buffered fragments
    uint32_t afr[2][2][4];   // [buf][mf][4]
    uint32_t bfr[2][8][2];   // [buf][nf][2]

    #define LDFRAG(buf, as, bs, ks)                                                 \
        do {                                                                        \
            int kb = (ks) * 32 + fkb;                                               \
            _Pragma("unroll")                                                       \
            for (int mf = 0; mf < 2; mf++) {                                        \
                uint32_t addr = smem_u32(                                           \
                    (as) + SWZ((wm * 32 + mf * 16 + frow) * 128 + kb));             \
                asm volatile(                                                       \
                    "ldmatrix.sync.aligned.m8n8.x4.shared.b16 {%0,%1,%2,%3}, [%4];" \
                    : "=r"(afr[buf][mf][0]), "=r"(afr[buf][mf][1]),                 \
                      "=r"(afr[buf][mf][2]), "=r"(afr[buf][mf][3])                  \
                    : "r"(addr));                                                   \
            }                                                                       \
            _Pragma("unroll")                                                       \
            for (int p = 0; p < 4; p++) {                                           \
                uint32_t r0, r1, r2, r3;                                            \
                uint32_t addr = smem_u32(                                           \
                    (bs) + SWZ((wn * 64 + p * 16 + frow) * 128 + kb));              \
                asm volatile(                                                       \
                    "ldmatrix.sync.aligned.m8n8.x4.shared.b16 {%0,%1,%2,%3}, [%4];" \
                    : "=r"(r0), "=r"(r1), "=r"(r2), "=r"(r3)                        \
                    : "r"(addr));                                                   \
                bfr[buf][2 * p][0] = r0; bfr[buf][2 * p + 1][0] = r1;               \
                bfr[buf][2 * p][1] = r2; bfr[buf][2 * p + 1][1] = r3;               \
            }                                                                       \
        } while (0)

    const int NITER = K_DIM / GBK;   // 16
    for (int it = 0; it < NITER; ++it) {
        int cur = it % STAGES;

        asm volatile("cp.async.wait_group %0;" :: "n"(1) : "memory");
        __syncthreads();

        if (it + 2 < NITER) ISSUE_STAGE((it + 2) % STAGES, (it + 2) * GBK);

        const char* as = As + cur * STAGE_BYTES;
        const char* bs = Bs + cur * STAGE_BYTES;

        LDFRAG(0, as, bs, 0);

        #pragma unroll
        for (int ks = 0; ks < 4; ks++) {          // four k16 steps per BK=64
            if (ks < 3) LDFRAG((ks + 1) & 1, as, bs, ks + 1);
            int fb = ks & 1;
            #pragma unroll
            for (int mf = 0; mf < 2; mf++)
                #pragma unroll
                for (int nf = 0; nf < 8; nf++)
                    asm volatile(
                        "mma.sync.aligned.m16n8k16.row.col.f32.f16.f16.f32 "
                        "{%0,%1,%2,%3}, {%4,%5,%6,%7}, {%8,%9}, {%0,%1,%2,%3};"
                        : "+f"(acc[mf][nf][0]), "+f"(acc[mf][nf][1]),
                          "+f"(acc[mf][nf][2]), "+f"(acc[mf][nf][3])
                        : "r"(afr[fb][mf][0]), "r"(afr[fb][mf][1]),
                          "r"(afr[fb][mf][2]), "r"(afr[fb][mf][3]),
                          "r"(bfr[fb][nf][0]), "r"(bfr[fb][nf][1]));
        }
    }

    // epilogue: + bias, relu
    #pragma unroll
    for (int mf = 0; mf < 2; mf++) {
        int row0 = bm + wm * 32 + mf * 16 + (lane >> 2);
        #pragma unroll
        for (int nf = 0; nf < 8; nf++) {
            int col = bn + wn * 64 + nf * 8 + (lane & 3) * 2;
            float b0 = __ldg(bias + col);
            float b1 = __ldg(bias + col + 1);
            if (row0 < M) {
                float2 o;
                o.x = fmaxf(acc[mf][nf][0] + b0, 0.f);
                o.y = fmaxf(acc[mf][nf][1] + b1, 0.f);
                *reinterpret_cast<float2*>(out + (size_t)row0 * OUT_DIM + col) = o;
            }
            if (row0 + 8 < M) {
                float2 o;
                o.x = fmaxf(acc[mf][nf][2] + b0, 0.f);
                o.y = fmaxf(acc[mf][nf][3] + b1, 0.f);
                *reinterpret_cast<float2*>(out + (size_t)(row0 + 8) * OUT_DIM + col) = o;
            }
        }
    }
}

// ---------------------------------------------------------------------------
extern "C" void kernel_launch(void* const* d_in, const int* in_sizes, int n_in,
                              void* d_out, int out_size) {
    const float* h      = (const float*)d_in[0];
    const float* basis  = (const float*)d_in[1];
    const float* w_comp = (const float*)d_in[2];
    const float* bias   = (const float*)d_in[3];
    const int*   src    = (const int*)d_in[4];
    const int*   dst    = (const int*)d_in[5];
    const int*   etype  = (const int*)d_in[6];
    float* out = (float*)d_out;

    int N = in_sizes[0] / IN_DIM;   // 20000
    int E = in_sizes[4];            // 320000

    static cudaStream_t s1 = nullptr, s2 = nullptr;
    static cudaEvent_t e0 = nullptr, e1 = nullptr, e2 = nullptr;
    static bool init_done = false;
    if (!init_done) {
        cudaFuncSetAttribute(gemm_tc_kernel,
                             cudaFuncAttributeMaxDynamicSharedMemorySize,
                             GEMM_SMEM_BYTES);
        cudaStreamCreateWithFlags(&s1, cudaStreamNonBlocking);
        cudaStreamCreateWithFlags(&s2, cudaStreamNonBlocking);
        cudaEventCreateWithFlags(&e0, cudaEventDisableTiming);
        cudaEventCreateWithFlags(&e1, cudaEventDisableTiming);
        cudaEventCreateWithFlags(&e2, cudaEventDisableTiming);
        init_done = true;
    }

    void* uptr = nullptr;
    cudaGetSymbolAddress(&uptr, g_U);
    __half* btp = nullptr;
    cudaGetSymbolAddress((void**)&btp, g_Bt);

    // fork: memset U on s1; transpose on s2 (joined only before GEMM)
    cudaEventRecord(e0, 0);
    cudaStreamWaitEvent(s1, e0, 0);
    cudaStreamWaitEvent(s2, e0, 0);

    cudaMemsetAsync(uptr, 0, (size_t)M_PAD * K_DIM * sizeof(__half), s1);  // #1
    cudaEventRecord(e1, s1);

    fold_kernel<<<(N * 32 + 255) / 256, 256>>>(h, w_comp, N);              // #2

    transpose_kernel<<<dim3(32, 8), dim3(32, 8), 0, s2>>>(basis);          // #3
    cudaEventRecord(e2, s2);

    cudaStreamWaitEvent(0, e1, 0);   // scatter needs zeroed U (+ fold on main)

    scatter_kernel<<<(E + 15) / 16, 256>>>(src, dst, etype, E);            // #4

    cudaStreamWaitEvent(0, e2, 0);   // GEMM needs Bt

    dim3 grid(M_PAD / GBM, OUT_DIM / GBN);   // 157 x 2
    gemm_tc_kernel<<<grid, 256, GEMM_SMEM_BYTES>>>(btp, bias, out, N);     // #5 (ncu)
}